// round 1
// baseline (speedup 1.0000x reference)
#include <cuda_runtime.h>
#include <math.h>

#define FIN  128
#define FHID 64
#define FOUT 40
#define NMAX 100000

// Scratch (allocation-free rule: __device__ globals)
__device__ float g_xw1 [NMAX * FHID];   // x @ W1
__device__ float g_agg1[NMAX * FHID];   // segment_sum layer 1
__device__ float g_hw2 [NMAX * FOUT];   // relu(agg1+b1) @ W2
__device__ float g_agg2[NMAX * FOUT];   // segment_sum layer 2
__device__ int   g_idx64;               // 1 if edge_index is int64, 0 if int32

// ---------------------------------------------------------------------------
// Detect edge_index dtype: for int64 little-endian values < 2^17, every odd
// 32-bit word is zero. For int32, odd words are random node ids (all-zero
// probability ~ (1e-5)^32 = 0).
// ---------------------------------------------------------------------------
__global__ void detect_kernel(const unsigned int* __restrict__ w) {
    if (threadIdx.x == 0 && blockIdx.x == 0) {
        int is64 = 1;
        #pragma unroll
        for (int i = 1; i < 64; i += 2) is64 &= (w[i] == 0u);
        g_idx64 = is64;
    }
}

// ---------------------------------------------------------------------------
// GEMM1: Y[M,64] = X[M,128] @ W[128,64].  One thread per row, W in smem,
// X staged through smem in K-chunks of 16 (padded stride 17: conflict-free).
// ---------------------------------------------------------------------------
__global__ void gemm1_kernel(const float* __restrict__ X,
                             const float* __restrict__ W,
                             float* __restrict__ Y, int M) {
    __shared__ float ws[FIN * FHID];      // 32 KB
    __shared__ float xs[128 * 17];        // 8.7 KB
    const int tid = threadIdx.x;
    const int row = blockIdx.x * 128 + tid;

    for (int i = tid; i < FIN * FHID; i += 128) ws[i] = W[i];

    float4 acc[FHID / 4];
    #pragma unroll
    for (int c = 0; c < FHID / 4; c++) acc[c] = make_float4(0.f, 0.f, 0.f, 0.f);

    const int rg = tid >> 4;   // 0..7
    const int il = tid & 15;   // 0..15

    for (int kc = 0; kc < FIN; kc += 16) {
        __syncthreads();
        #pragma unroll
        for (int rr = 0; rr < 16; rr++) {
            int r = rr * 8 + rg;
            int grow = blockIdx.x * 128 + r;
            xs[r * 17 + il] = (grow < M) ? X[(size_t)grow * FIN + kc + il] : 0.f;
        }
        __syncthreads();
        #pragma unroll
        for (int i = 0; i < 16; i++) {
            float xk = xs[tid * 17 + i];
            const float4* wrow = (const float4*)(ws + (kc + i) * FHID);
            #pragma unroll
            for (int c = 0; c < FHID / 4; c++) {
                float4 w4 = wrow[c];
                acc[c].x += xk * w4.x; acc[c].y += xk * w4.y;
                acc[c].z += xk * w4.z; acc[c].w += xk * w4.w;
            }
        }
    }
    if (row < M) {
        float4* yo = (float4*)(Y + (size_t)row * FHID);
        #pragma unroll
        for (int c = 0; c < FHID / 4; c++) yo[c] = acc[c];
    }
}

// ---------------------------------------------------------------------------
// GEMM2 (fused h = relu(agg1 + b1)): Y[M,40] = h[M,64] @ W2[64,40]
// ---------------------------------------------------------------------------
__global__ void gemm2_kernel(const float* __restrict__ AGG,
                             const float* __restrict__ B1,
                             const float* __restrict__ W,
                             float* __restrict__ Y, int M) {
    __shared__ float ws[FHID * FOUT];     // 10.25 KB
    __shared__ float xs[128 * 17];
    const int tid = threadIdx.x;
    const int row = blockIdx.x * 128 + tid;

    for (int i = tid; i < FHID * FOUT; i += 128) ws[i] = W[i];

    float4 acc[FOUT / 4];
    #pragma unroll
    for (int c = 0; c < FOUT / 4; c++) acc[c] = make_float4(0.f, 0.f, 0.f, 0.f);

    const int rg = tid >> 4;
    const int il = tid & 15;

    for (int kc = 0; kc < FHID; kc += 16) {
        __syncthreads();
        #pragma unroll
        for (int rr = 0; rr < 16; rr++) {
            int r = rr * 8 + rg;
            int grow = blockIdx.x * 128 + r;
            float v = 0.f;
            if (grow < M)
                v = fmaxf(AGG[(size_t)grow * FHID + kc + il] + __ldg(&B1[kc + il]), 0.f);
            xs[r * 17 + il] = v;
        }
        __syncthreads();
        #pragma unroll
        for (int i = 0; i < 16; i++) {
            float xk = xs[tid * 17 + i];
            const float4* wrow = (const float4*)(ws + (kc + i) * FOUT);
            #pragma unroll
            for (int c = 0; c < FOUT / 4; c++) {
                float4 w4 = wrow[c];
                acc[c].x += xk * w4.x; acc[c].y += xk * w4.y;
                acc[c].z += xk * w4.z; acc[c].w += xk * w4.w;
            }
        }
    }
    if (row < M) {
        float4* yo = (float4*)(Y + (size_t)row * FOUT);   // 160B rows: 16B aligned
        #pragma unroll
        for (int c = 0; c < FOUT / 4; c++) yo[c] = acc[c];
    }
}

// ---------------------------------------------------------------------------
// Edge scatter-add, 16 float4-chunks per edge (layer 1, 64 feats).
// Vector RED: 1 L2 atomic op per 16B instead of 4.
// ---------------------------------------------------------------------------
__device__ __forceinline__ void red_add_v4(float* p, float4 v) {
    asm volatile("red.global.add.v4.f32 [%0], {%1,%2,%3,%4};"
                 :: "l"(p), "f"(v.x), "f"(v.y), "f"(v.z), "f"(v.w) : "memory");
}

__device__ __forceinline__ void load_edge(const void* ei, int E, int e, int& s, int& d) {
    if (g_idx64) {
        const long long* p = (const long long*)ei;
        s = (int)__ldg(&p[e]);
        d = (int)__ldg(&p[E + e]);
    } else {
        const int* p = (const int*)ei;
        s = __ldg(&p[e]);
        d = __ldg(&p[E + e]);
    }
}

__global__ void scatter1_kernel(const void* __restrict__ ei, int E,
                                const float* __restrict__ XW,
                                float* __restrict__ AGG) {
    int gid = blockIdx.x * blockDim.x + threadIdx.x;
    int e = gid >> 4;
    if (e >= E) return;
    int c = gid & 15;
    int s, d;
    load_edge(ei, E, e, s, d);
    float4 v = __ldg((const float4*)(XW + (size_t)s * FHID) + c);
    red_add_v4(AGG + (size_t)d * FHID + c * 4, v);
}

// Layer 2: 10 float4-chunks per edge (40 feats)
__global__ void scatter2_kernel(const void* __restrict__ ei, int E,
                                const float* __restrict__ XW,
                                float* __restrict__ AGG) {
    int gid = blockIdx.x * blockDim.x + threadIdx.x;
    int e = gid / 10;
    if (e >= E) return;
    int c = gid - e * 10;
    int s, d;
    load_edge(ei, E, e, s, d);
    float4 v = __ldg((const float4*)(XW + (size_t)s * FOUT) + c);
    red_add_v4(AGG + (size_t)d * FOUT + c * 4, v);
}

// ---------------------------------------------------------------------------
// out = log_softmax(agg2 + b2), one warp per row (40 cols: lane + lane+32)
// ---------------------------------------------------------------------------
__global__ void lsm_kernel(const float* __restrict__ AGG,
                           const float* __restrict__ B2,
                           float* __restrict__ OUT, int M) {
    int w = (blockIdx.x * blockDim.x + threadIdx.x) >> 5;
    int lane = threadIdx.x & 31;
    if (w >= M) return;
    const float* in = AGG + (size_t)w * FOUT;
    float v0 = in[lane] + __ldg(&B2[lane]);
    float v1 = (lane < FOUT - 32) ? in[32 + lane] + __ldg(&B2[32 + lane]) : -INFINITY;
    float m = fmaxf(v0, v1);
    #pragma unroll
    for (int o = 16; o; o >>= 1) m = fmaxf(m, __shfl_xor_sync(0xffffffffu, m, o));
    float s = __expf(v0 - m) + ((lane < FOUT - 32) ? __expf(v1 - m) : 0.f);
    #pragma unroll
    for (int o = 16; o; o >>= 1) s += __shfl_xor_sync(0xffffffffu, s, o);
    float lse = m + logf(s);
    float* o = OUT + (size_t)w * FOUT;
    o[lane] = v0 - lse;
    if (lane < FOUT - 32) o[32 + lane] = v1 - lse;
}

// ---------------------------------------------------------------------------
extern "C" void kernel_launch(void* const* d_in, const int* in_sizes, int n_in,
                              void* d_out, int out_size) {
    const float* x  = (const float*)d_in[0];
    const void*  ei = d_in[1];                 // int32 or int64, detected on device
    const float* W1 = (const float*)d_in[2];
    const float* b1 = (const float*)d_in[3];
    const float* W2 = (const float*)d_in[4];
    const float* b2 = (const float*)d_in[5];
    float* out = (float*)d_out;

    const int M = in_sizes[0] / FIN;           // 100000
    const int E = in_sizes[1] / 2;             // 1600000

    float *xw1, *agg1, *hw2, *agg2;
    cudaGetSymbolAddress((void**)&xw1,  g_xw1);
    cudaGetSymbolAddress((void**)&agg1, g_agg1);
    cudaGetSymbolAddress((void**)&hw2,  g_hw2);
    cudaGetSymbolAddress((void**)&agg2, g_agg2);

    cudaMemsetAsync(agg1, 0, sizeof(float) * (size_t)M * FHID);
    cudaMemsetAsync(agg2, 0, sizeof(float) * (size_t)M * FOUT);

    detect_kernel<<<1, 32>>>((const unsigned int*)ei);

    gemm1_kernel<<<(M + 127) / 128, 128>>>(x, W1, xw1, M);

    {
        long long work = (long long)E * 16;
        int blocks = (int)((work + 255) / 256);
        scatter1_kernel<<<blocks, 256>>>(ei, E, xw1, agg1);
    }

    gemm2_kernel<<<(M + 127) / 128, 128>>>(agg1, b1, W2, hw2, M);

    {
        long long work = (long long)E * 10;
        int blocks = (int)((work + 255) / 256);
        scatter2_kernel<<<blocks, 256>>>(ei, E, hw2, agg2);
    }

    {
        long long work = (long long)M * 32;
        int blocks = (int)((work + 255) / 256);
        lsm_kernel<<<blocks, 256>>>(agg2, b2, out, M);
    }
}